// round 6
// baseline (speedup 1.0000x reference)
#include <cuda_runtime.h>

// ---------------------------------------------------------------------------
// Single fused kernel. Per-block, thread 0 folds all model parameters into
// 10 float4s in shared memory (scale/shift folded into next layer's weights;
// quantum circuit collapsed to 5 trig coefficients), then every thread
// processes 4 samples.
//
// Quantum head: post-encoding circuit (RY layers + CZ) is a fixed REAL 4x4
// matrix M; <Z0>+<Z1> = 2(p00 - p11) needs only rows 0,3. Expanding in
// full-angle trig and using sinA sinB = cos(A-B) - cosA cosB:
//   q = K0 + K1 c0 + K2 c1 + (K3-K4) c0 c1 + K4 cos(x0-x1)
// -> 3 MUFU.COS per sample. Backbone: 10 MUFU.TANH per sample.
// ---------------------------------------------------------------------------

__device__ __forceinline__ float htanh(float x) {
    float y;
    asm("tanh.approx.f32 %0, %1;" : "=f"(y) : "f"(x));
    return y;
}

__global__ __launch_bounds__(256)
void fused_kernel(const float* __restrict__ x,      // [N,2]
                  const float* __restrict__ Ws,     // [5,2,2]
                  const float* __restrict__ bs,     // [5,2]
                  const float* __restrict__ scales, // [5,2]
                  const float* __restrict__ shifts, // [5,2]
                  const float* __restrict__ Wf,     // [1,2]
                  const float* __restrict__ bf,     // [1]
                  const float* __restrict__ theta,  // [2,2]
                  float* __restrict__ out, int n)
{
    __shared__ float4 sp[10];

    if (threadIdx.x == 0) {
        // ---- fused backbone params ----------------------------------------
        float W[5][2][2], B[5][2];
#pragma unroll
        for (int l = 0; l < 5; l++) {
            float s0 = (l == 0) ? 1.0f : scales[2 * (l - 1) + 0];
            float s1 = (l == 0) ? 1.0f : scales[2 * (l - 1) + 1];
            float h0 = (l == 0) ? 0.0f : shifts[2 * (l - 1) + 0];
            float h1 = (l == 0) ? 0.0f : shifts[2 * (l - 1) + 1];
#pragma unroll
            for (int i = 0; i < 2; i++) {
                float w0 = Ws[4 * l + 2 * i + 0];
                float w1 = Ws[4 * l + 2 * i + 1];
                W[l][i][0] = w0 * s0;
                W[l][i][1] = w1 * s1;
                B[l][i] = w0 * h0 + w1 * h1 + bs[2 * l + i];
            }
        }
        float wf0 = Wf[0] * scales[8], wf1 = Wf[1] * scales[9];
        float bff = Wf[0] * shifts[8] + Wf[1] * shifts[9] + bf[0];

        // ---- quantum circuit matrix (RY layers + CZ, all real) ------------
        float M[4][4];
#pragma unroll
        for (int i = 0; i < 4; i++)
#pragma unroll
            for (int j = 0; j < 4; j++) M[i][j] = (i == j) ? 1.0f : 0.0f;
#pragma unroll
        for (int d = 0; d < 2; d++) {                 // Q_DEPTH = 2
            float a0 = theta[2 * d + 0] * 0.5f;
            float a1 = theta[2 * d + 1] * 0.5f;
            float c0 = cosf(a0), s0 = sinf(a0);
            float c1 = cosf(a1), s1 = sinf(a1);
#pragma unroll
            for (int q1 = 0; q1 < 2; q1++)            // RY on qubit 0
#pragma unroll
                for (int j = 0; j < 4; j++) {
                    float r0 = M[2 * q1 + 0][j], r1 = M[2 * q1 + 1][j];
                    M[2 * q1 + 0][j] = c0 * r0 - s0 * r1;
                    M[2 * q1 + 1][j] = s0 * r0 + c0 * r1;
                }
#pragma unroll
            for (int q0 = 0; q0 < 2; q0++)            // RY on qubit 1
#pragma unroll
                for (int j = 0; j < 4; j++) {
                    float r0 = M[q0][j], r1 = M[2 + q0][j];
                    M[q0][j]     = c1 * r0 - s1 * r1;
                    M[2 + q0][j] = s1 * r0 + c1 * r1;
                }
#pragma unroll
            for (int j = 0; j < 4; j++) M[3][j] = -M[3][j];  // CZ
        }

        // ---- q(x0,x1) = K0 + K1 c0 + K2 c1 + K3 c0c1 + K4 s0s1 ------------
        float a0 = M[0][0] * M[0][0], b0 = M[0][3] * M[0][3];
        float c0 = M[0][1] * M[0][1], d0 = M[0][2] * M[0][2];
        float e0 = M[0][1] * M[0][2] - M[0][0] * M[0][3];
        float a3 = M[3][0] * M[3][0], b3 = M[3][3] * M[3][3];
        float c3 = M[3][1] * M[3][1], d3 = M[3][2] * M[3][2];
        float e3 = M[3][1] * M[3][2] - M[3][0] * M[3][3];
        float K0 = 0.5f * ((a0 + b0 + c0 + d0) - (a3 + b3 + c3 + d3));
        float K1 = 0.5f * ((a0 - b0 - c0 + d0) - (a3 - b3 - c3 + d3));
        float K2 = 0.5f * ((a0 - b0 + c0 - d0) - (a3 - b3 + c3 - d3));
        float K3 = 0.5f * ((a0 + b0 - c0 - d0) - (a3 + b3 - c3 - d3));
        float K4 = e0 - e3;

#pragma unroll
        for (int l = 0; l < 5; l++)
            sp[l] = make_float4(W[l][0][0], W[l][0][1], W[l][1][0], W[l][1][1]);
        sp[5] = make_float4(B[0][0], B[0][1], B[1][0], B[1][1]);
        sp[6] = make_float4(B[2][0], B[2][1], B[3][0], B[3][1]);
        sp[7] = make_float4(B[4][0], B[4][1], wf0, wf1);
        sp[8] = make_float4(bff, K0, K1, K2);
        sp[9] = make_float4(K3 - K4, K4, 0.0f, 0.0f);
    }
    __syncthreads();

    float4 P0 = sp[0], P1 = sp[1], P2 = sp[2], P3 = sp[3], P4 = sp[4];
    float4 P5 = sp[5], P6 = sp[6], P7 = sp[7], P8 = sp[8], P9 = sp[9];

    int t = blockIdx.x * blockDim.x + threadIdx.x;   // 4 samples per thread
    int s0 = t * 4;
    if (s0 >= n) return;

    float u[4], v[4];                 // raw inputs per sample
    if (s0 + 3 < n) {
        const float4* x4 = (const float4*)x;
        float4 xa = __ldg(&x4[2 * t + 0]);            // samples s0, s0+1
        float4 xb = __ldg(&x4[2 * t + 1]);            // samples s0+2, s0+3
        u[0] = xa.x; v[0] = xa.y;  u[1] = xa.z; v[1] = xa.w;
        u[2] = xb.x; v[2] = xb.y;  u[3] = xb.z; v[3] = xb.w;
    } else {
#pragma unroll
        for (int k = 0; k < 4; k++) {
            int s = s0 + k;
            u[k] = (s < n) ? x[2 * s + 0] : 0.0f;
            v[k] = (s < n) ? x[2 * s + 1] : 0.0f;
        }
    }

    float r[4];
#pragma unroll
    for (int k = 0; k < 4; k++) {
        // -------- classical backbone ---------------------------------------
        float h0 = u[k], h1 = v[k];
        float p0, p1;
        p0 = fmaf(P0.x, h0, fmaf(P0.y, h1, P5.x));
        p1 = fmaf(P0.z, h0, fmaf(P0.w, h1, P5.y));
        h0 = htanh(p0); h1 = htanh(p1);
        p0 = fmaf(P1.x, h0, fmaf(P1.y, h1, P5.z));
        p1 = fmaf(P1.z, h0, fmaf(P1.w, h1, P5.w));
        h0 = htanh(p0); h1 = htanh(p1);
        p0 = fmaf(P2.x, h0, fmaf(P2.y, h1, P6.x));
        p1 = fmaf(P2.z, h0, fmaf(P2.w, h1, P6.y));
        h0 = htanh(p0); h1 = htanh(p1);
        p0 = fmaf(P3.x, h0, fmaf(P3.y, h1, P6.z));
        p1 = fmaf(P3.z, h0, fmaf(P3.w, h1, P6.w));
        h0 = htanh(p0); h1 = htanh(p1);
        p0 = fmaf(P4.x, h0, fmaf(P4.y, h1, P7.x));
        p1 = fmaf(P4.z, h0, fmaf(P4.w, h1, P7.y));
        h0 = htanh(p0); h1 = htanh(p1);

        // -------- quantum head: 3 cos per sample ---------------------------
        float c0 = __cosf(u[k]);
        float c1 = __cosf(v[k]);
        float cd = __cosf(u[k] - v[k]);

        float q = fmaf(P8.z, c0, P8.y);       // K0 + K1 c0
        q = fmaf(P8.w, c1, q);                // + K2 c1
        q = fmaf(P9.x, c0 * c1, q);           // + (K3-K4) c0 c1
        q = fmaf(P9.y, cd, q);                // + K4 cos(x0-x1)

        r[k] = fmaf(P7.z, h0, fmaf(P7.w, h1, P8.x)) + q;
    }

    if (s0 + 3 < n) {
        ((float4*)out)[t] = make_float4(r[0], r[1], r[2], r[3]);
    } else {
#pragma unroll
        for (int k = 0; k < 4; k++)
            if (s0 + k < n) out[s0 + k] = r[k];
    }
}

extern "C" void kernel_launch(void* const* d_in, const int* in_sizes, int n_in,
                              void* d_out, int out_size)
{
    const float* x      = (const float*)d_in[0];
    const float* Ws     = (const float*)d_in[1];
    const float* bs     = (const float*)d_in[2];
    const float* scales = (const float*)d_in[3];
    const float* shifts = (const float*)d_in[4];
    const float* Wf     = (const float*)d_in[5];
    const float* bf     = (const float*)d_in[6];
    const float* theta  = (const float*)d_in[7];

    int n = out_size;                         // N samples
    int nthreads = (n + 3) / 4;
    const int threads = 256;
    int blocks = (nthreads + threads - 1) / threads;

    fused_kernel<<<blocks, threads>>>(x, Ws, bs, scales, shifts, Wf, bf, theta,
                                      (float*)d_out, n);
}

// round 12
// speedup vs baseline: 1.1725x; 1.1725x over previous
#include <cuda_runtime.h>

// ---------------------------------------------------------------------------
// Two kernels. setup_kernel (1 thread) folds all model params into 10 float4s
// in a __device__ global: scale/shift folded into the next layer's weights,
// quantum circuit collapsed to trig coefficients. fused_kernel stages those
// 10 float4s into shared memory once per block (threads 0-9), then each
// thread processes 2 samples.
//
// Quantum head: post-encoding circuit (RY layers + CZ) is a fixed REAL 4x4
// matrix M; <Z0>+<Z1> = 2(p00 - p11) needs only rows 0,3. Expanding in
// full-angle trig and using sinA sinB = cos(A-B) - cosA cosB:
//   q = K0 + K1 c0 + K2 c1 + (K3-K4) c0 c1 + K4 cos(x0-x1)
// -> 3 MUFU.COS per sample. Backbone: 10 MUFU.TANH per sample.
// ---------------------------------------------------------------------------

__device__ float4 g_p[10];

__global__ void setup_kernel(const float* __restrict__ Ws,
                             const float* __restrict__ bs,
                             const float* __restrict__ scales,
                             const float* __restrict__ shifts,
                             const float* __restrict__ Wf,
                             const float* __restrict__ bf,
                             const float* __restrict__ theta)
{
    if (threadIdx.x != 0) return;

    // ---- fused backbone params --------------------------------------------
    float W[5][2][2], B[5][2];
#pragma unroll
    for (int l = 0; l < 5; l++) {
        float s0 = (l == 0) ? 1.0f : scales[2 * (l - 1) + 0];
        float s1 = (l == 0) ? 1.0f : scales[2 * (l - 1) + 1];
        float h0 = (l == 0) ? 0.0f : shifts[2 * (l - 1) + 0];
        float h1 = (l == 0) ? 0.0f : shifts[2 * (l - 1) + 1];
#pragma unroll
        for (int i = 0; i < 2; i++) {
            float w0 = Ws[4 * l + 2 * i + 0];
            float w1 = Ws[4 * l + 2 * i + 1];
            W[l][i][0] = w0 * s0;
            W[l][i][1] = w1 * s1;
            B[l][i] = w0 * h0 + w1 * h1 + bs[2 * l + i];
        }
    }
    float wf0 = Wf[0] * scales[8], wf1 = Wf[1] * scales[9];
    float bff = Wf[0] * shifts[8] + Wf[1] * shifts[9] + bf[0];

    // ---- quantum circuit matrix (RY layers + CZ, all real) ----------------
    float M[4][4];
#pragma unroll
    for (int i = 0; i < 4; i++)
#pragma unroll
        for (int j = 0; j < 4; j++) M[i][j] = (i == j) ? 1.0f : 0.0f;
#pragma unroll
    for (int d = 0; d < 2; d++) {                 // Q_DEPTH = 2
        // fast sincos: theta angles are O(1); __sincosf err ~1e-7 here,
        // negligible vs the 1e-3 threshold, and avoids slow-path trig in
        // this serial single-thread kernel.
        float c0, s0, c1, s1;
        __sincosf(theta[2 * d + 0] * 0.5f, &s0, &c0);
        __sincosf(theta[2 * d + 1] * 0.5f, &s1, &c1);
#pragma unroll
        for (int q1 = 0; q1 < 2; q1++)            // RY on qubit 0
#pragma unroll
            for (int j = 0; j < 4; j++) {
                float r0 = M[2 * q1 + 0][j], r1 = M[2 * q1 + 1][j];
                M[2 * q1 + 0][j] = c0 * r0 - s0 * r1;
                M[2 * q1 + 1][j] = s0 * r0 + c0 * r1;
            }
#pragma unroll
        for (int q0 = 0; q0 < 2; q0++)            // RY on qubit 1
#pragma unroll
            for (int j = 0; j < 4; j++) {
                float r0 = M[q0][j], r1 = M[2 + q0][j];
                M[q0][j]     = c1 * r0 - s1 * r1;
                M[2 + q0][j] = s1 * r0 + c1 * r1;
            }
#pragma unroll
        for (int j = 0; j < 4; j++) M[3][j] = -M[3][j];  // CZ
    }

    // ---- q(x0,x1) = K0 + K1 c0 + K2 c1 + K3 c0c1 + K4 s0s1 ----------------
    float a0 = M[0][0] * M[0][0], b0 = M[0][3] * M[0][3];
    float c0 = M[0][1] * M[0][1], d0 = M[0][2] * M[0][2];
    float e0 = M[0][1] * M[0][2] - M[0][0] * M[0][3];
    float a3 = M[3][0] * M[3][0], b3 = M[3][3] * M[3][3];
    float c3 = M[3][1] * M[3][1], d3 = M[3][2] * M[3][2];
    float e3 = M[3][1] * M[3][2] - M[3][0] * M[3][3];
    float K0 = 0.5f * ((a0 + b0 + c0 + d0) - (a3 + b3 + c3 + d3));
    float K1 = 0.5f * ((a0 - b0 - c0 + d0) - (a3 - b3 - c3 + d3));
    float K2 = 0.5f * ((a0 - b0 + c0 - d0) - (a3 - b3 + c3 - d3));
    float K3 = 0.5f * ((a0 + b0 - c0 - d0) - (a3 + b3 - c3 - d3));
    float K4 = e0 - e3;

#pragma unroll
    for (int l = 0; l < 5; l++)
        g_p[l] = make_float4(W[l][0][0], W[l][0][1], W[l][1][0], W[l][1][1]);
    g_p[5] = make_float4(B[0][0], B[0][1], B[1][0], B[1][1]);
    g_p[6] = make_float4(B[2][0], B[2][1], B[3][0], B[3][1]);
    g_p[7] = make_float4(B[4][0], B[4][1], wf0, wf1);
    g_p[8] = make_float4(bff, K0, K1, K2);
    g_p[9] = make_float4(K3 - K4, K4, 0.0f, 0.0f);
}

// Hardware tanh: single MUFU.TANH.
__device__ __forceinline__ float htanh(float x) {
    float y;
    asm("tanh.approx.f32 %0, %1;" : "=f"(y) : "f"(x));
    return y;
}

__global__ __launch_bounds__(256)
void fused_kernel(const float4* __restrict__ x, float2* __restrict__ out,
                  int npairs)
{
    __shared__ float4 sp[10];
    if (threadIdx.x < 10) sp[threadIdx.x] = g_p[threadIdx.x];
    __syncthreads();

    int i = blockIdx.x * blockDim.x + threadIdx.x;
    if (i >= npairs) return;

    float4 xv = __ldg(&x[i]);                 // two samples: (x,y) and (z,w)

    float4 P0 = sp[0], P1 = sp[1], P2 = sp[2], P3 = sp[3], P4 = sp[4];
    float4 P5 = sp[5], P6 = sp[6], P7 = sp[7], P8 = sp[8], P9 = sp[9];

    float ha0 = xv.x, ha1 = xv.y;
    float hb0 = xv.z, hb1 = xv.w;

#define LAYER(W, B0, B1)                                                \
    {                                                                   \
        float pa0 = fmaf((W).x, ha0, fmaf((W).y, ha1, (B0)));           \
        float pa1 = fmaf((W).z, ha0, fmaf((W).w, ha1, (B1)));           \
        float pb0 = fmaf((W).x, hb0, fmaf((W).y, hb1, (B0)));           \
        float pb1 = fmaf((W).z, hb0, fmaf((W).w, hb1, (B1)));           \
        ha0 = htanh(pa0); ha1 = htanh(pa1);                             \
        hb0 = htanh(pb0); hb1 = htanh(pb1);                             \
    }

    LAYER(P0, P5.x, P5.y)
    LAYER(P1, P5.z, P5.w)
    LAYER(P2, P6.x, P6.y)
    LAYER(P3, P6.z, P6.w)
    LAYER(P4, P7.x, P7.y)
#undef LAYER

    float ca = fmaf(P7.z, ha0, fmaf(P7.w, ha1, P8.x));
    float cb = fmaf(P7.z, hb0, fmaf(P7.w, hb1, P8.x));

    // quantum head: q = K0 + K1 c0 + K2 c1 + (K3-K4) c0c1 + K4 cos(x0-x1)
    float ca0 = __cosf(xv.x);
    float ca1 = __cosf(xv.y);
    float cad = __cosf(xv.x - xv.y);
    float cb0 = __cosf(xv.z);
    float cb1 = __cosf(xv.w);
    float cbd = __cosf(xv.z - xv.w);

    float qa = fmaf(P8.z, ca0, P8.y);
    qa = fmaf(P8.w, ca1, qa);
    qa = fmaf(P9.x, ca0 * ca1, qa);
    qa = fmaf(P9.y, cad, qa);

    float qb = fmaf(P8.z, cb0, P8.y);
    qb = fmaf(P8.w, cb1, qb);
    qb = fmaf(P9.x, cb0 * cb1, qb);
    qb = fmaf(P9.y, cbd, qb);

    out[i] = make_float2(ca + qa, cb + qb);
}

extern "C" void kernel_launch(void* const* d_in, const int* in_sizes, int n_in,
                              void* d_out, int out_size)
{
    const float* x      = (const float*)d_in[0];   // [N, 2]
    const float* Ws     = (const float*)d_in[1];   // [5, 2, 2]
    const float* bs     = (const float*)d_in[2];   // [5, 2]
    const float* scales = (const float*)d_in[3];   // [5, 2]
    const float* shifts = (const float*)d_in[4];   // [5, 2]
    const float* Wf     = (const float*)d_in[5];   // [1, 2]
    const float* bf     = (const float*)d_in[6];   // [1]
    const float* theta  = (const float*)d_in[7];   // [2, 2]

    int n = out_size;                 // N samples (even)
    int npairs = n >> 1;

    setup_kernel<<<1, 32>>>(Ws, bs, scales, shifts, Wf, bf, theta);

    const int threads = 256;
    int blocks = (npairs + threads - 1) / threads;
    fused_kernel<<<blocks, threads>>>((const float4*)x, (float2*)d_out, npairs);
}

// round 13
// speedup vs baseline: 1.2420x; 1.0592x over previous
#include <cuda_runtime.h>
#include <cuda_fp16.h>

// ---------------------------------------------------------------------------
// Two kernels. setup_kernel (1 thread) folds all model params into 10 float4s
// in a __device__ global. fused_kernel stages them into shared memory per
// block, then each thread processes 2 samples.
//
// MUFU reduction: layers 0-3 use packed tanh.approx.f16x2 (both samples'
// same-neuron activations in one MUFU op); layer 4 stays f32 tanh since its
// error is undamped. Quantum head: 3 MUFU.COS per sample via
//   q = K0 + K1 c0 + K2 c1 + (K3-K4) c0 c1 + K4 cos(x0-x1).
// MUFU ops/thread: 26 -> 18.
// ---------------------------------------------------------------------------

__device__ float4 g_p[10];

__global__ void setup_kernel(const float* __restrict__ Ws,
                             const float* __restrict__ bs,
                             const float* __restrict__ scales,
                             const float* __restrict__ shifts,
                             const float* __restrict__ Wf,
                             const float* __restrict__ bf,
                             const float* __restrict__ theta)
{
    if (threadIdx.x != 0) return;

    // ---- fused backbone params --------------------------------------------
    float W[5][2][2], B[5][2];
#pragma unroll
    for (int l = 0; l < 5; l++) {
        float s0 = (l == 0) ? 1.0f : scales[2 * (l - 1) + 0];
        float s1 = (l == 0) ? 1.0f : scales[2 * (l - 1) + 1];
        float h0 = (l == 0) ? 0.0f : shifts[2 * (l - 1) + 0];
        float h1 = (l == 0) ? 0.0f : shifts[2 * (l - 1) + 1];
#pragma unroll
        for (int i = 0; i < 2; i++) {
            float w0 = Ws[4 * l + 2 * i + 0];
            float w1 = Ws[4 * l + 2 * i + 1];
            W[l][i][0] = w0 * s0;
            W[l][i][1] = w1 * s1;
            B[l][i] = w0 * h0 + w1 * h1 + bs[2 * l + i];
        }
    }
    float wf0 = Wf[0] * scales[8], wf1 = Wf[1] * scales[9];
    float bff = Wf[0] * shifts[8] + Wf[1] * shifts[9] + bf[0];

    // ---- quantum circuit matrix (RY layers + CZ, all real) ----------------
    float M[4][4];
#pragma unroll
    for (int i = 0; i < 4; i++)
#pragma unroll
        for (int j = 0; j < 4; j++) M[i][j] = (i == j) ? 1.0f : 0.0f;
#pragma unroll
    for (int d = 0; d < 2; d++) {                 // Q_DEPTH = 2
        float c0, s0, c1, s1;
        __sincosf(theta[2 * d + 0] * 0.5f, &s0, &c0);
        __sincosf(theta[2 * d + 1] * 0.5f, &s1, &c1);
#pragma unroll
        for (int q1 = 0; q1 < 2; q1++)            // RY on qubit 0
#pragma unroll
            for (int j = 0; j < 4; j++) {
                float r0 = M[2 * q1 + 0][j], r1 = M[2 * q1 + 1][j];
                M[2 * q1 + 0][j] = c0 * r0 - s0 * r1;
                M[2 * q1 + 1][j] = s0 * r0 + c0 * r1;
            }
#pragma unroll
        for (int q0 = 0; q0 < 2; q0++)            // RY on qubit 1
#pragma unroll
            for (int j = 0; j < 4; j++) {
                float r0 = M[q0][j], r1 = M[2 + q0][j];
                M[q0][j]     = c1 * r0 - s1 * r1;
                M[2 + q0][j] = s1 * r0 + c1 * r1;
            }
#pragma unroll
        for (int j = 0; j < 4; j++) M[3][j] = -M[3][j];  // CZ
    }

    // ---- q(x0,x1) = K0 + K1 c0 + K2 c1 + K3 c0c1 + K4 s0s1 ----------------
    float a0 = M[0][0] * M[0][0], b0 = M[0][3] * M[0][3];
    float c0 = M[0][1] * M[0][1], d0 = M[0][2] * M[0][2];
    float e0 = M[0][1] * M[0][2] - M[0][0] * M[0][3];
    float a3 = M[3][0] * M[3][0], b3 = M[3][3] * M[3][3];
    float c3 = M[3][1] * M[3][1], d3 = M[3][2] * M[3][2];
    float e3 = M[3][1] * M[3][2] - M[3][0] * M[3][3];
    float K0 = 0.5f * ((a0 + b0 + c0 + d0) - (a3 + b3 + c3 + d3));
    float K1 = 0.5f * ((a0 - b0 - c0 + d0) - (a3 - b3 - c3 + d3));
    float K2 = 0.5f * ((a0 - b0 + c0 - d0) - (a3 - b3 + c3 - d3));
    float K3 = 0.5f * ((a0 + b0 - c0 - d0) - (a3 + b3 - c3 - d3));
    float K4 = e0 - e3;

#pragma unroll
    for (int l = 0; l < 5; l++)
        g_p[l] = make_float4(W[l][0][0], W[l][0][1], W[l][1][0], W[l][1][1]);
    g_p[5] = make_float4(B[0][0], B[0][1], B[1][0], B[1][1]);
    g_p[6] = make_float4(B[2][0], B[2][1], B[3][0], B[3][1]);
    g_p[7] = make_float4(B[4][0], B[4][1], wf0, wf1);
    g_p[8] = make_float4(bff, K0, K1, K2);
    g_p[9] = make_float4(K3 - K4, K4, 0.0f, 0.0f);
}

// f32 hardware tanh: single MUFU op.
__device__ __forceinline__ float htanh(float x) {
    float y;
    asm("tanh.approx.f32 %0, %1;" : "=f"(y) : "f"(x));
    return y;
}

// Packed tanh: two values through one MUFU op (f16x2).
// Returns (tanh(a), tanh(b)) as float2 (.x = a's, .y = b's).
__device__ __forceinline__ float2 htanh2(float a, float b) {
    __half2 h = __floats2half2_rn(a, b);            // a -> lo, b -> hi
    unsigned int u = *reinterpret_cast<unsigned int*>(&h);
    asm("tanh.approx.f16x2 %0, %0;" : "+r"(u));
    __half2 t = *reinterpret_cast<__half2*>(&u);
    return __half22float2(t);
}

__global__ __launch_bounds__(256)
void fused_kernel(const float4* __restrict__ x, float2* __restrict__ out,
                  int npairs)
{
    __shared__ float4 sp[10];
    if (threadIdx.x < 10) sp[threadIdx.x] = g_p[threadIdx.x];
    __syncthreads();

    int i = blockIdx.x * blockDim.x + threadIdx.x;
    if (i >= npairs) return;

    float4 xv = __ldg(&x[i]);                 // two samples: (x,y) and (z,w)

    float4 P0 = sp[0], P1 = sp[1], P2 = sp[2], P3 = sp[3], P4 = sp[4];
    float4 P5 = sp[5], P6 = sp[6], P7 = sp[7], P8 = sp[8], P9 = sp[9];

    float ha0 = xv.x, ha1 = xv.y;
    float hb0 = xv.z, hb1 = xv.w;

    // Layers 0-3: packed f16x2 tanh (2 MUFU ops/layer instead of 4).
#define LAYER_H2(W, B0, B1)                                             \
    {                                                                   \
        float pa0 = fmaf((W).x, ha0, fmaf((W).y, ha1, (B0)));           \
        float pa1 = fmaf((W).z, ha0, fmaf((W).w, ha1, (B1)));           \
        float pb0 = fmaf((W).x, hb0, fmaf((W).y, hb1, (B0)));           \
        float pb1 = fmaf((W).z, hb0, fmaf((W).w, hb1, (B1)));           \
        float2 t0 = htanh2(pa0, pb0);                                   \
        float2 t1 = htanh2(pa1, pb1);                                   \
        ha0 = t0.x; hb0 = t0.y; ha1 = t1.x; hb1 = t1.y;                 \
    }

    LAYER_H2(P0, P5.x, P5.y)
    LAYER_H2(P1, P5.z, P5.w)
    LAYER_H2(P2, P6.x, P6.y)
    LAYER_H2(P3, P6.z, P6.w)
#undef LAYER_H2

    // Layer 4 (last): f32 tanh — its error is undamped by later layers.
    {
        float pa0 = fmaf(P4.x, ha0, fmaf(P4.y, ha1, P7.x));
        float pa1 = fmaf(P4.z, ha0, fmaf(P4.w, ha1, P7.y));
        float pb0 = fmaf(P4.x, hb0, fmaf(P4.y, hb1, P7.x));
        float pb1 = fmaf(P4.z, hb0, fmaf(P4.w, hb1, P7.y));
        ha0 = htanh(pa0); ha1 = htanh(pa1);
        hb0 = htanh(pb0); hb1 = htanh(pb1);
    }

    float ca = fmaf(P7.z, ha0, fmaf(P7.w, ha1, P8.x));
    float cb = fmaf(P7.z, hb0, fmaf(P7.w, hb1, P8.x));

    // quantum head: q = K0 + K1 c0 + K2 c1 + (K3-K4) c0c1 + K4 cos(x0-x1)
    float ca0 = __cosf(xv.x);
    float ca1 = __cosf(xv.y);
    float cad = __cosf(xv.x - xv.y);
    float cb0 = __cosf(xv.z);
    float cb1 = __cosf(xv.w);
    float cbd = __cosf(xv.z - xv.w);

    float qa = fmaf(P8.z, ca0, P8.y);
    qa = fmaf(P8.w, ca1, qa);
    qa = fmaf(P9.x, ca0 * ca1, qa);
    qa = fmaf(P9.y, cad, qa);

    float qb = fmaf(P8.z, cb0, P8.y);
    qb = fmaf(P8.w, cb1, qb);
    qb = fmaf(P9.x, cb0 * cb1, qb);
    qb = fmaf(P9.y, cbd, qb);

    out[i] = make_float2(ca + qa, cb + qb);
}

extern "C" void kernel_launch(void* const* d_in, const int* in_sizes, int n_in,
                              void* d_out, int out_size)
{
    const float* x      = (const float*)d_in[0];   // [N, 2]
    const float* Ws     = (const float*)d_in[1];   // [5, 2, 2]
    const float* bs     = (const float*)d_in[2];   // [5, 2]
    const float* scales = (const float*)d_in[3];   // [5, 2]
    const float* shifts = (const float*)d_in[4];   // [5, 2]
    const float* Wf     = (const float*)d_in[5];   // [1, 2]
    const float* bf     = (const float*)d_in[6];   // [1]
    const float* theta  = (const float*)d_in[7];   // [2, 2]

    int n = out_size;                 // N samples (even)
    int npairs = n >> 1;

    setup_kernel<<<1, 32>>>(Ws, bs, scales, shifts, Wf, bf, theta);

    const int threads = 256;
    int blocks = (npairs + threads - 1) / threads;
    fused_kernel<<<blocks, threads>>>((const float4*)x, (float2*)d_out, npairs);
}